// round 14
// baseline (speedup 1.0000x reference)
#include <cuda_runtime.h>
#include <math.h>

// ---------------------------------------------------------------------------
// BatchShapingLoss, single fused kernel, 128 thr x 4 elems (4x ILP).
// Evaluation (validated rel_err ~1e-7):
//   pcdf(z) = z^0.6 * Q(w) + A999 * (z/w)^0.6,  z = s-EPS, w = 1-z
//   Q fitted per octave of w (exponent-bit indexed), degree-13 Chebyshev,
//   host-fit in double; 4 MUFU + ~26 FMA per element.
// Rank: 1024-bin counting sort (hist + scan + scatter + intra-bin fix,
//   deterministic tie-break on element row).
// Finalize: single packed u64 atomic (block counter in high bits), self-reset.
// ---------------------------------------------------------------------------

#define EPSV  1e-10f
#define NOCT  32
#define NC    14
#define NB    1024
#define FXS   274877906944.0   // 2^38

struct Coefs {
    float ct[NC * NOCT];   // [j][octave], 448 floats
    float a999;
};

__device__ unsigned long long g_acc = 0ULL;

static __device__ __forceinline__ float lg2f(float x) {
    float r; asm("lg2.approx.f32 %0, %1;" : "=f"(r) : "f"(x)); return r;
}
static __device__ __forceinline__ float ex2f(float x) {
    float r; asm("ex2.approx.f32 %0, %1;" : "=f"(r) : "f"(x)); return r;
}

static __device__ __forceinline__ float eval_pcdf(float v, const float* sc, float a999) {
    float z  = fmaxf(v - EPSV, 0.0f);
    float wv = 1.0f - z;
    unsigned int ui = __float_as_uint(wv);
    int iv = 126 - (int)(ui >> 23);
    iv = iv < 0 ? 0 : (iv > NOCT - 1 ? NOCT - 1 : iv);
    float t  = fmaf((float)(ui & 0x7fffffu), 0x1p-22f, -1.0f);
    float t2 = t + t;
    float b1 = 0.0f, b2 = 0.0f;
    #pragma unroll
    for (int j = NC - 1; j >= 1; j--) {
        float bb = fmaf(t2, b1, sc[j * NOCT + iv] - b2);
        b2 = b1; b1 = bb;
    }
    float Q  = fmaf(t, b1, sc[iv] - b2);
    float lz = lg2f(z);
    float lw = lg2f(wv);
    return fmaf(ex2f(0.6f * lz), Q, a999 * ex2f(0.6f * (lz - lw)));
}

__global__ void __launch_bounds__(128) fused_kernel(const float* __restrict__ x,
                                                    const Coefs cf,
                                                    float* __restrict__ out)
{
    __shared__ unsigned int cnt[NB];       // counts -> slot counters
    __shared__ unsigned int pre[NB + 4];   // exclusive prefix (+sentinel)
    __shared__ float        sval[512];
    __shared__ unsigned int sidx[512];
    __shared__ float        sc[NC * NOCT];
    __shared__ float        wsum[4];
    __shared__ unsigned int woff[4];

    int tid = threadIdx.x;
    int c   = blockIdx.x;

    float v0 = __ldg(&x[ tid        * 128 + c]);
    float v1 = __ldg(&x[(tid + 128) * 128 + c]);
    float v2 = __ldg(&x[(tid + 256) * 128 + c]);
    float v3 = __ldg(&x[(tid + 384) * 128 + c]);

    // stage coefficients via vector loads (112 uint4 = 448 floats)
    if (tid < 112) ((uint4*)sc)[tid] = ((const uint4*)cf.ct)[tid];

    ((uint4*)cnt)[tid]       = make_uint4(0u, 0u, 0u, 0u);
    ((uint4*)cnt)[tid + 128] = make_uint4(0u, 0u, 0u, 0u);
    __syncthreads();                                            // B1

    int b0 = (int)(v0 * (float)NB); b0 = b0 < 0 ? 0 : (b0 > NB - 1 ? NB - 1 : b0);
    int b1i = (int)(v1 * (float)NB); b1i = b1i < 0 ? 0 : (b1i > NB - 1 ? NB - 1 : b1i);
    int b2i = (int)(v2 * (float)NB); b2i = b2i < 0 ? 0 : (b2i > NB - 1 ? NB - 1 : b2i);
    int b3i = (int)(v3 * (float)NB); b3i = b3i < 0 ? 0 : (b3i > NB - 1 ? NB - 1 : b3i);
    atomicAdd(&cnt[b0], 1u);
    atomicAdd(&cnt[b1i], 1u);
    atomicAdd(&cnt[b2i], 1u);
    atomicAdd(&cnt[b3i], 1u);
    __syncthreads();                                            // B2

    // ---- scan: 8 bins/thread ----
    uint4 a = ((uint4*)cnt)[2 * tid];
    uint4 b = ((uint4*)cnt)[2 * tid + 1];
    unsigned int e1 = a.x, e2 = e1 + a.y, e3 = e2 + a.z, e4 = e3 + a.w;
    unsigned int e5 = e4 + b.x, e6 = e5 + b.y, e7 = e6 + b.z;
    unsigned int tot = e7 + b.w;

    unsigned int incl = tot;
    #pragma unroll
    for (int o = 1; o < 32; o <<= 1) {
        unsigned int n = __shfl_up_sync(0xffffffffu, incl, o);
        if ((tid & 31) >= o) incl += n;
    }
    int wid = tid >> 5;
    if ((tid & 31) == 31) woff[wid] = incl;
    unsigned int wex = incl - tot;
    __syncthreads();                                            // B3

    uint4 wa = ((uint4*)woff)[0];
    unsigned int wsums[4] = {wa.x, wa.y, wa.z, wa.w};
    unsigned int base0 = wex;
    #pragma unroll
    for (int w = 0; w < 4; w++) base0 += (w < wid) ? wsums[w] : 0u;

    uint4 p0 = make_uint4(base0, base0 + e1, base0 + e2, base0 + e3);
    uint4 p1 = make_uint4(base0 + e4, base0 + e5, base0 + e6, base0 + e7);
    ((uint4*)pre)[2 * tid]     = p0;
    ((uint4*)pre)[2 * tid + 1] = p1;
    ((uint4*)cnt)[2 * tid]     = p0;
    ((uint4*)cnt)[2 * tid + 1] = p1;
    if (tid == 0) pre[NB] = 512u;
    __syncthreads();                                            // B4

    unsigned int s0 = atomicAdd(&cnt[b0], 1u);
    sval[s0] = v0; sidx[s0] = (unsigned int)tid;
    unsigned int s1 = atomicAdd(&cnt[b1i], 1u);
    sval[s1] = v1; sidx[s1] = (unsigned int)(tid + 128);
    unsigned int s2 = atomicAdd(&cnt[b2i], 1u);
    sval[s2] = v2; sidx[s2] = (unsigned int)(tid + 256);
    unsigned int s3 = atomicAdd(&cnt[b3i], 1u);
    sval[s3] = v3; sidx[s3] = (unsigned int)(tid + 384);
    __syncthreads();                                            // B5

    // ---- ranks (deterministic: value, tie-break original row) ----
    unsigned int rank0, rank1, rank2, rank3;
    {
        unsigned int rb = pre[b0], m = pre[b0 + 1] - rb; rank0 = rb;
        if (m > 1u)
            for (unsigned int j = rb; j < rb + m; j++) {
                float vj = sval[j]; unsigned int ij = sidx[j];
                rank0 += (vj < v0) || (vj == v0 && ij < (unsigned int)tid);
            }
    }
    {
        unsigned int rb = pre[b1i], m = pre[b1i + 1] - rb; rank1 = rb;
        if (m > 1u)
            for (unsigned int j = rb; j < rb + m; j++) {
                float vj = sval[j]; unsigned int ij = sidx[j];
                rank1 += (vj < v1) || (vj == v1 && ij < (unsigned int)(tid + 128));
            }
    }
    {
        unsigned int rb = pre[b2i], m = pre[b2i + 1] - rb; rank2 = rb;
        if (m > 1u)
            for (unsigned int j = rb; j < rb + m; j++) {
                float vj = sval[j]; unsigned int ij = sidx[j];
                rank2 += (vj < v2) || (vj == v2 && ij < (unsigned int)(tid + 256));
            }
    }
    {
        unsigned int rb = pre[b3i], m = pre[b3i + 1] - rb; rank3 = rb;
        if (m > 1u)
            for (unsigned int j = rb; j < rb + m; j++) {
                float vj = sval[j]; unsigned int ij = sidx[j];
                rank3 += (vj < v3) || (vj == v3 && ij < (unsigned int)(tid + 384));
            }
    }

    // ---- evaluation (4 independent chains -> ILP) ----
    float p0f = eval_pcdf(v0, sc, cf.a999);
    float p1f = eval_pcdf(v1, sc, cf.a999);
    float p2f = eval_pcdf(v2, sc, cf.a999);
    float p3f = eval_pcdf(v3, sc, cf.a999);
    float d0 = p0f - (float)(rank0 + 1u) * (1.0f / 513.0f);
    float d1 = p1f - (float)(rank1 + 1u) * (1.0f / 513.0f);
    float d2 = p2f - (float)(rank2 + 1u) * (1.0f / 513.0f);
    float d3 = p3f - (float)(rank3 + 1u) * (1.0f / 513.0f);
    float sq = fmaf(d0, d0, d1 * d1) + fmaf(d2, d2, d3 * d3);

    // ---- reduction + packed single-atomic finalize ----
    #pragma unroll
    for (int o = 16; o > 0; o >>= 1) sq += __shfl_xor_sync(0xffffffffu, sq, o);
    if ((tid & 31) == 0) wsum[wid] = sq;
    __syncthreads();                                            // B6
    if (tid == 0) {
        float t = wsum[0] + wsum[1] + wsum[2] + wsum[3];
        unsigned long long fx =
            (unsigned long long)__double2ll_rn((double)t * FXS)
            + (1ULL << 56);
        unsigned long long newv = atomicAdd(&g_acc, fx) + fx;
        if ((newv >> 56) == 128ULL) {          // last block: newv has full sum
            out[0] = (float)((double)(newv & 0x00FFFFFFFFFFFFFFULL)
                             * (1.0 / FXS) * (1.0 / 512.0));
            atomicExch(&g_acc, 0ULL);          // reset for next graph replay
        }
    }
}

extern "C" void kernel_launch(void* const* d_in, const int* in_sizes, int n_in,
                              void* d_out, int out_size) {
    const float* x = (const float*)d_in[0];

    double betaln = lgamma(0.6) + lgamma(0.4) - lgamma(1.0);
    double pref   = exp(-betaln) * pow(999.0, -0.6);
    const double PI = acos(-1.0);

    Coefs cf;
    cf.a999 = (float)(pref * 0.5 * pow(999.0, -0.4));

    static double ak[999];
    for (int k = 1; k <= 998; k++) {
        double wk = (k == 1) ? 0.5 : 1.0;
        ak[k] = pref * wk * pow((double)k, -0.4);
    }

    for (int ivv = 0; ivv < NOCT; ivv++) {
        int    e  = -1 - ivv;
        double s2 = ldexp(1.0, e);
        double wc = 1.5 * s2, wh = 0.5 * s2;
        double fv[NC];
        for (int i = 0; i < NC; i++) {
            double xi = cos(PI * (i + 0.5) / NC);
            double zz = 1.0 - (wc + wh * xi);
            double s  = 0.0;
            for (int k = 1; k <= 998; k++)
                s += ak[k] * pow(1.0 - (double)k * zz / 999.0, -0.6);
            fv[i] = s;
        }
        for (int j = 0; j < NC; j++) {
            double aa = 0.0;
            for (int i = 0; i < NC; i++)
                aa += fv[i] * cos(PI * j * (i + 0.5) / NC);
            aa *= 2.0 / NC;
            if (j == 0) aa *= 0.5;
            cf.ct[j * NOCT + ivv] = (float)aa;
        }
    }

    fused_kernel<<<128, 128>>>(x, cf, (float*)d_out);
}

// round 15
// speedup vs baseline: 1.0772x; 1.0772x over previous
#include <cuda_runtime.h>
#include <math.h>

// ---------------------------------------------------------------------------
// BatchShapingLoss, single fused kernel. 256 thr x 2 elems (best config).
// Evaluation:
//   pcdf(z) = z^0.6 * Q(w) + A999 * (z/w)^0.6,  z = s-EPS, w = 1-z
//   Q fitted per octave of w (exponent-bit indexed), degree-9 Chebyshev
//   (rho>=3 per octave -> trunc ~2e-5 rel, loss rel_err ~1e-5 << 1e-3).
// Rank: 2048-bin counting sort; after scatter, cnt[] IS the inclusive
//   prefix -> no separate pre[] array. Deterministic tie-break on row.
// Finalize: single packed u64 atomic (block counter in high bits), self-reset.
// ---------------------------------------------------------------------------

#define EPSV  1e-10f
#define NOCT  32
#define NC    10
#define NB    2048
#define FXS   274877906944.0   // 2^38

struct Coefs {
    float ct[NC * NOCT];   // [j][octave], 320 floats
    float a999;
};

__device__ unsigned long long g_acc = 0ULL;

static __device__ __forceinline__ float lg2f(float x) {
    float r; asm("lg2.approx.f32 %0, %1;" : "=f"(r) : "f"(x)); return r;
}
static __device__ __forceinline__ float ex2f(float x) {
    float r; asm("ex2.approx.f32 %0, %1;" : "=f"(r) : "f"(x)); return r;
}

static __device__ __forceinline__ float eval_pcdf(float v, const float* sc, float a999) {
    float z  = fmaxf(v - EPSV, 0.0f);
    float wv = 1.0f - z;
    unsigned int ui = __float_as_uint(wv);
    int iv = 126 - (int)(ui >> 23);
    iv = iv < 0 ? 0 : (iv > NOCT - 1 ? NOCT - 1 : iv);
    float t  = fmaf((float)(ui & 0x7fffffu), 0x1p-22f, -1.0f);
    float t2 = t + t;
    float b1 = 0.0f, b2 = 0.0f;
    #pragma unroll
    for (int j = NC - 1; j >= 1; j--) {
        float bb = fmaf(t2, b1, sc[j * NOCT + iv] - b2);
        b2 = b1; b1 = bb;
    }
    float Q  = fmaf(t, b1, sc[iv] - b2);
    float lz = lg2f(z);
    float lw = lg2f(wv);
    return fmaf(ex2f(0.6f * lz), Q, a999 * ex2f(0.6f * (lz - lw)));
}

__global__ void __launch_bounds__(256) fused_kernel(const float* __restrict__ x,
                                                    const Coefs cf,
                                                    float* __restrict__ out)
{
    __shared__ unsigned int cnt[NB];       // counts -> excl prefix -> incl prefix
    __shared__ float        sval[512];
    __shared__ unsigned int sidx[512];
    __shared__ float        sc[NC * NOCT];
    __shared__ float        wsum[8];
    __shared__ unsigned int woff[8];

    int tid = threadIdx.x;
    int c   = blockIdx.x;
    float v0 = __ldg(&x[tid * 128 + c]);
    float v1 = __ldg(&x[(tid + 256) * 128 + c]);

    // stage coefficients (80 uint4 = 320 floats) while loads are in flight
    if (tid < NC * NOCT / 4) ((uint4*)sc)[tid] = ((const uint4*)cf.ct)[tid];

    ((uint4*)cnt)[tid]       = make_uint4(0u, 0u, 0u, 0u);
    ((uint4*)cnt)[tid + 256] = make_uint4(0u, 0u, 0u, 0u);
    __syncthreads();                                            // B1

    int bin0 = (int)(v0 * (float)NB); bin0 = bin0 < 0 ? 0 : (bin0 > NB - 1 ? NB - 1 : bin0);
    int bin1 = (int)(v1 * (float)NB); bin1 = bin1 < 0 ? 0 : (bin1 > NB - 1 ? NB - 1 : bin1);
    atomicAdd(&cnt[bin0], 1u);
    atomicAdd(&cnt[bin1], 1u);
    __syncthreads();                                            // B2

    // ---- scan: 8 bins/thread ----
    uint4 a = ((uint4*)cnt)[2 * tid];
    uint4 b = ((uint4*)cnt)[2 * tid + 1];
    unsigned int e1 = a.x, e2 = e1 + a.y, e3 = e2 + a.z, e4 = e3 + a.w;
    unsigned int e5 = e4 + b.x, e6 = e5 + b.y, e7 = e6 + b.z;
    unsigned int tot = e7 + b.w;

    unsigned int incl = tot;
    #pragma unroll
    for (int o = 1; o < 32; o <<= 1) {
        unsigned int n = __shfl_up_sync(0xffffffffu, incl, o);
        if ((tid & 31) >= o) incl += n;
    }
    int wid = tid >> 5;
    if ((tid & 31) == 31) woff[wid] = incl;
    unsigned int wex = incl - tot;
    __syncthreads();                                            // B3

    uint4 wa = ((uint4*)woff)[0];
    uint4 wb = ((uint4*)woff)[1];
    unsigned int ws8[8] = {wa.x, wa.y, wa.z, wa.w, wb.x, wb.y, wb.z, wb.w};
    unsigned int base0 = wex;
    #pragma unroll
    for (int w = 0; w < 8; w++) base0 += (w < wid) ? ws8[w] : 0u;

    // write exclusive prefixes back into cnt (scatter turns them inclusive)
    ((uint4*)cnt)[2 * tid]     = make_uint4(base0, base0 + e1, base0 + e2, base0 + e3);
    ((uint4*)cnt)[2 * tid + 1] = make_uint4(base0 + e4, base0 + e5, base0 + e6, base0 + e7);
    __syncthreads();                                            // B4

    unsigned int s0 = atomicAdd(&cnt[bin0], 1u);
    sval[s0] = v0; sidx[s0] = (unsigned int)tid;
    unsigned int s1 = atomicAdd(&cnt[bin1], 1u);
    sval[s1] = v1; sidx[s1] = (unsigned int)(tid + 256);
    __syncthreads();                                            // B5
    // now cnt[b] = inclusive prefix

    // ---- ranks (deterministic: value, tie-break original row) ----
    unsigned int hi0 = cnt[bin0];
    unsigned int rb0 = bin0 ? cnt[bin0 - 1] : 0u;
    unsigned int rank0 = rb0;
    if (hi0 - rb0 > 1u)
        for (unsigned int j = rb0; j < hi0; j++) {
            float vj = sval[j]; unsigned int ij = sidx[j];
            rank0 += (vj < v0) || (vj == v0 && ij < (unsigned int)tid);
        }
    unsigned int hi1 = cnt[bin1];
    unsigned int rb1 = bin1 ? cnt[bin1 - 1] : 0u;
    unsigned int rank1 = rb1;
    if (hi1 - rb1 > 1u)
        for (unsigned int j = rb1; j < hi1; j++) {
            float vj = sval[j]; unsigned int ij = sidx[j];
            rank1 += (vj < v1) || (vj == v1 && ij < (unsigned int)(tid + 256));
        }

    // ---- evaluation (2x ILP) ----
    float p0f = eval_pcdf(v0, sc, cf.a999);
    float p1f = eval_pcdf(v1, sc, cf.a999);
    float d0  = p0f - (float)(rank0 + 1u) * (1.0f / 513.0f);
    float d1  = p1f - (float)(rank1 + 1u) * (1.0f / 513.0f);
    float sq  = fmaf(d0, d0, d1 * d1);

    // ---- reduction + packed single-atomic finalize ----
    #pragma unroll
    for (int o = 16; o > 0; o >>= 1) sq += __shfl_xor_sync(0xffffffffu, sq, o);
    if ((tid & 31) == 0) wsum[wid] = sq;
    __syncthreads();                                            // B6
    if (tid == 0) {
        float t = wsum[0] + wsum[1] + wsum[2] + wsum[3]
                + wsum[4] + wsum[5] + wsum[6] + wsum[7];
        unsigned long long fx =
            (unsigned long long)__double2ll_rn((double)t * FXS)
            + (1ULL << 56);
        unsigned long long newv = atomicAdd(&g_acc, fx) + fx;
        if ((newv >> 56) == 128ULL) {          // last block: newv has full sum
            out[0] = (float)((double)(newv & 0x00FFFFFFFFFFFFFFULL)
                             * (1.0 / FXS) * (1.0 / 512.0));
            atomicExch(&g_acc, 0ULL);          // reset for next graph replay
        }
    }
}

extern "C" void kernel_launch(void* const* d_in, const int* in_sizes, int n_in,
                              void* d_out, int out_size) {
    const float* x = (const float*)d_in[0];

    double betaln = lgamma(0.6) + lgamma(0.4) - lgamma(1.0);
    double pref   = exp(-betaln) * pow(999.0, -0.6);
    const double PI = acos(-1.0);

    Coefs cf;
    cf.a999 = (float)(pref * 0.5 * pow(999.0, -0.4));

    static double ak[999];
    for (int k = 1; k <= 998; k++) {
        double wk = (k == 1) ? 0.5 : 1.0;
        ak[k] = pref * wk * pow((double)k, -0.4);
    }

    for (int ivv = 0; ivv < NOCT; ivv++) {
        int    e  = -1 - ivv;
        double s2 = ldexp(1.0, e);
        double wc = 1.5 * s2, wh = 0.5 * s2;
        double fv[NC];
        for (int i = 0; i < NC; i++) {
            double xi = cos(PI * (i + 0.5) / NC);
            double zz = 1.0 - (wc + wh * xi);
            double s  = 0.0;
            for (int k = 1; k <= 998; k++)
                s += ak[k] * pow(1.0 - (double)k * zz / 999.0, -0.6);
            fv[i] = s;
        }
        for (int j = 0; j < NC; j++) {
            double aa = 0.0;
            for (int i = 0; i < NC; i++)
                aa += fv[i] * cos(PI * j * (i + 0.5) / NC);
            aa *= 2.0 / NC;
            if (j == 0) aa *= 0.5;
            cf.ct[j * NOCT + ivv] = (float)aa;
        }
    }

    fused_kernel<<<128, 256>>>(x, cf, (float*)d_out);
}